// round 16
// baseline (speedup 1.0000x reference)
#include <cuda_runtime.h>
#include <cuda_fp16.h>
#include <cstdint>

// ---------------- scratch (static __device__, no allocs) ----------------
// X in MMA-A-fragment-interleaved records: rec(m, rb, kb) = 256 halfs (512B),
// lane l owns halfs [l*8, l*8+8) in m16n8k16 a-frag register order:
//   reg0=(r0,k0..1) reg1=(r0+8,k0..1) reg2=(r0,k0+8..9) reg3=(r0+8,k0+8..9),
//   r0 = l>>2, k0 = (l&3)*2.  rb = global 16-row block (0..2047), kb = 16-k block.
#define XFN (3u*2048u*32u*256u)
#define WN (3u*512u*512u)
__device__ __half g_xfhi[XFN];
__device__ __half g_xflo[XFN];   // V third unused
__device__ __half g_wthi[WN];    // [m][n][k] fp16, K-major (W transposed)
__device__ __half g_wtlo[WN];

__device__ __forceinline__ uint32_t smem_u32(const void* p) {
    uint32_t a;
    asm("{ .reg .u64 t; cvta.to.shared.u64 t, %1; cvt.u32.u64 %0, t; }" : "=r"(a) : "l"(p));
    return a;
}

#define LDSM4(r, a) \
    asm volatile("ldmatrix.sync.aligned.m8n8.x4.shared.b16 {%0,%1,%2,%3}, [%4];" \
        : "=r"((r)[0]), "=r"((r)[1]), "=r"((r)[2]), "=r"((r)[3]) : "r"(a))

#define MMA16816(c, a, b0, b1) \
    asm volatile("mma.sync.aligned.m16n8k16.row.col.f32.f16.f16.f32 " \
        "{%0,%1,%2,%3},{%4,%5,%6,%7},{%8,%9},{%0,%1,%2,%3};" \
        : "+f"((c)[0]), "+f"((c)[1]), "+f"((c)[2]), "+f"((c)[3]) \
        : "r"((a)[0]), "r"((a)[1]), "r"((a)[2]), "r"((a)[3]), "r"(b0), "r"(b1))

#define CPA16(dst, src) \
    asm volatile("cp.async.cg.shared.global [%0], [%1], 16;" :: "r"(dst), "l"(src))
#define CPCOMMIT() asm volatile("cp.async.commit_group;" ::: "memory")
#define CPWAIT(n)  asm volatile("cp.async.wait_group %0;" :: "n"(n) : "memory")

// ---------------- fused prep kernel ----------------
// blocks [0, 24576): X a-frag split — one thread per (m, rb, kb, lane)
// blocks [24576, 27648): W transpose+split, 256 elems per block
#define XFB 24576
__global__ void __launch_bounds__(256)
prep_all(const float* __restrict__ Qs, const float* __restrict__ Ks,
         const float* __restrict__ Vs, const int* __restrict__ Qlen,
         const float* __restrict__ WQ, const float* __restrict__ WK,
         const float* __restrict__ WV) {
    if (blockIdx.x < XFB) {
        int idx = blockIdx.x * 256 + threadIdx.x;   // 3*2048*32*32
        int l   = idx & 31;
        int kb  = (idx >> 5) & 31;
        int rbm = idx >> 10;                        // m*2048 + rb
        int m   = rbm >> 11;
        int gr0 = (rbm & 2047) << 4;                // row base within matrix
        int bb  = gr0 >> 12, s = gr0 & 4095;
        if (s >= ((Qlen[bb] + 63) & ~63)) return;   // never read by GEMM
        const float* X = (m == 0) ? Qs : (m == 1) ? Ks : Vs;
        int r0 = l >> 2, k0 = (l & 3) * 2;
        const float* p0 = X + (size_t)(gr0 + r0) * 512 + kb * 16;
        const float* p8 = p0 + 8 * 512;
        float f[8] = { p0[k0], p0[k0 + 1], p8[k0], p8[k0 + 1],
                       p0[k0 + 8], p0[k0 + 9], p8[k0 + 8], p8[k0 + 9] };
        union { __half h[8]; uint4 u; } H, L;
        #pragma unroll
        for (int i = 0; i < 8; i++) {
            H.h[i] = __float2half_rn(f[i]);
            L.h[i] = __float2half_rn(f[i] - __half2float(H.h[i]));
        }
        size_t o = ((size_t)rbm * 32 + kb) * 256 + l * 8;
        *(uint4*)(g_xfhi + o) = H.u;
        if (m < 2) *(uint4*)(g_xflo + o) = L.u;
    } else {
        int idx = (blockIdx.x - XFB) * 256 + threadIdx.x;   // 3*512*512, [m][n][k]
        int m = idx >> 18;
        int r = idx & 262143;
        int n = r >> 9, k = r & 511;
        const float* W = (m == 0) ? WQ : (m == 1) ? WK : WV;
        float x = W[(size_t)k * 512 + n];
        __half h = __float2half_rn(x);
        g_wthi[idx] = h;
        if (m < 2) g_wtlo[idx] = __float2half_rn(x - __half2float(h));
    }
}

// ---------------- fused GEMM (HMMA) + softmax epilogue ----------------
// CTA: 64 rows x 1 head (N=64), 256 threads, 8 warps (warp tile 16x32), 2 CTAs/SM.
// A (X hi/lo): DIRECT coalesced LDG.128 from fragment-interleaved records — no smem.
// B (W hi/lo): cp.async 3-stage ring; ONE barrier/chunk; cpaW(c+2) post-barrier
//   (slot (c+2)%3 == (c-1)%3, readers past barrier c; != c%3, (c+1)%3).
// Q/K 3-product fp16 split; V single product; V_len culling (bit-exact output).
// W tile layout: 64 rows x 64B, phys 16B-col = c ^ ((r>>1)&3)  (round-10 proven).
#define WQHI 0
#define WQLO 4096
#define WKHI 8192
#define WKLO 12288
#define WVHI 16384
#define WS_B 20480
#define SMEM_T 61440
#define NCHUNK  16
#define ESTR    68               // floats per row in epilogue smem

__global__ void __launch_bounds__(256, 2)
gemm_attn(const int* __restrict__ Qlen, const int* __restrict__ Vlen, float* __restrict__ out) {
    extern __shared__ __align__(16) char dsm[];

    const int h = blockIdx.x;                  // head 0..7 (fastest -> X L2 reuse)
    const int tile = blockIdx.y;               // 0..511
    const int b = tile >> 6;
    const int s0 = (tile & 63) << 6;
    const int tid = threadIdx.x;
    const int qlen = Qlen[b];
    float* outbase = out + ((size_t)(b * 4096 + s0)) * 512 + h * 64;

    if (s0 >= qlen) {                          // whole tile masked: write zeros
        #pragma unroll
        for (int i = 0; i < 4; i++) {
            int lin = tid + i * 256;
            int r = lin >> 4, c4 = lin & 15;
            *(float4*)(outbase + (size_t)r * 512 + c4 * 4) = make_float4(0.f, 0.f, 0.f, 0.f);
        }
        return;
    }

    const int vlen = Vlen[b];
    const int nQK = vlen;                      // head-cols of Q/K needed
    const int nV  = (vlen == 0) ? 64 : vlen;   // head-cols of V needed
    const int nWQK = (nQK + 15) & ~15;         // W rows to load (LDSM coverage)
    const int nWV  = (nV + 15) & ~15;

    const uint32_t sbase = smem_u32(dsm);
    const int lane = tid & 31, wid = tid >> 5;
    const int wm = wid >> 1, wn = wid & 1;     // warp tile: rows 16*wm, cols 32*wn
    const int cbw = wn * 32;                   // col base of this warp

    // B-side ldmatrix mapping (swizzled, round-10 proven)
    const int rB = wn * 32 + ((lane >> 4) & 1) * 8 + (lane & 7);
    const int cB = (lane >> 3) & 1;
    const int swB = (rB >> 1) & 3;
    uint32_t offB[2];
    #pragma unroll
    for (int ks = 0; ks < 2; ks++)
        offB[ks] = (uint32_t)(rB * 64 + (((ks * 2 + cB) ^ swB) << 4));

    // A-side fragment record addressing
    const int rbw = ((b * 4096 + s0) >> 4) + wm;   // this warp's global 16-row block
    const size_t lby = (size_t)(lane * 8);
    auto xoff = [&](int m, int kb) {
        return ((size_t)((m * 2048 + rbw) * 32 + kb)) * 256 + lby;
    };

    float acc[3][4][4];
    #pragma unroll
    for (int m = 0; m < 3; m++)
        #pragma unroll
        for (int nt = 0; nt < 4; nt++)
            #pragma unroll
            for (int q = 0; q < 4; q++) acc[m][nt][q] = 0.f;

    // W loader: thread -> row tid>>2 (0..63), 16B-col tid&3; 1 CPA16 per tile
    const int lr = tid >> 2, cc = tid & 3;
    const uint32_t po = (uint32_t)(lr << 6) + ((((uint32_t)cc) ^ ((lr >> 1) & 3)) << 4);

    auto cpaW = [&](int c) {
        const int kk0 = c << 5;
        const uint32_t wb = sbase + (c % 3) * WS_B;
        const size_t w0 = ((size_t)(0 * 512 + h * 64 + lr)) * 512 + kk0 + cc * 8;
        const size_t w1 = ((size_t)(1 * 512 + h * 64 + lr)) * 512 + kk0 + cc * 8;
        const size_t w2 = ((size_t)(2 * 512 + h * 64 + lr)) * 512 + kk0 + cc * 8;
        if (lr < nWQK) {
            CPA16(wb + WQHI + po, g_wthi + w0);
            CPA16(wb + WQLO + po, g_wtlo + w0);
            CPA16(wb + WKHI + po, g_wthi + w1);
            CPA16(wb + WKLO + po, g_wtlo + w1);
        }
        if (lr < nWV) CPA16(wb + WVHI + po, g_wthi + w2);
        CPCOMMIT();
    };

    auto compute = [&](int c) {
        const uint32_t wb = sbase + (c % 3) * WS_B;
        const int kb0 = c * 2;
        // issue ALL a-frag LDGs up front (MLP); consumed per phase below
        uint4 aQH[2], aQL[2], aKH[2], aKL[2], aVH[2];
        if (cbw < nQK) {
            aQH[0] = *(const uint4*)(g_xfhi + xoff(0, kb0));
            aQH[1] = *(const uint4*)(g_xfhi + xoff(0, kb0 + 1));
            aQL[0] = *(const uint4*)(g_xflo + xoff(0, kb0));
            aQL[1] = *(const uint4*)(g_xflo + xoff(0, kb0 + 1));
            aKH[0] = *(const uint4*)(g_xfhi + xoff(1, kb0));
            aKH[1] = *(const uint4*)(g_xfhi + xoff(1, kb0 + 1));
            aKL[0] = *(const uint4*)(g_xflo + xoff(1, kb0));
            aKL[1] = *(const uint4*)(g_xflo + xoff(1, kb0 + 1));
        }
        if (cbw < nV) {
            aVH[0] = *(const uint4*)(g_xfhi + xoff(2, kb0));
            aVH[1] = *(const uint4*)(g_xfhi + xoff(2, kb0 + 1));
        }
        #pragma unroll
        for (int ks = 0; ks < 2; ks++) {
            uint32_t bH[2][4], bL[2][4];
            if (cbw < nQK) {
                // ---- Q: 3 products ----
                LDSM4(bH[0], wb + WQHI + offB[ks]);
                LDSM4(bL[0], wb + WQLO + offB[ks]);
                if (cbw + 16 < nQK) {
                    LDSM4(bH[1], wb + WQHI + offB[ks] + 1024);
                    LDSM4(bL[1], wb + WQLO + offB[ks] + 1024);
                }
                const uint32_t* aH = (const uint32_t*)&aQH[ks];
                const uint32_t* aL = (const uint32_t*)&aQL[ks];
                #pragma unroll
                for (int nt = 0; nt < 4; nt++) {
                    if (cbw + nt * 8 < nQK) {
                        const int nb = nt >> 1, p = (nt & 1) * 2;
                        MMA16816(acc[0][nt], aH, bH[nb][p], bH[nb][p + 1]);
                        MMA16816(acc[0][nt], aH, bL[nb][p], bL[nb][p + 1]);
                        MMA16816(acc[0][nt], aL, bH[nb][p], bH[nb][p + 1]);
                    }
                }
                // ---- K: 3 products ----
                LDSM4(bH[0], wb + WKHI + offB[ks]);
                LDSM4(bL[0], wb + WKLO + offB[ks]);
                if (cbw + 16 < nQK) {
                    LDSM4(bH[1], wb + WKHI + offB[ks] + 1024);
                    LDSM4(bL[1], wb + WKLO + offB[ks] + 1024);
                }
                const uint32_t* cH = (const uint32_t*)&aKH[ks];
                const uint32_t* cL = (const uint32_t*)&aKL[ks];
                #pragma unroll
                for (int nt = 0; nt < 4; nt++) {
                    if (cbw + nt * 8 < nQK) {
                        const int nb = nt >> 1, p = (nt & 1) * 2;
                        MMA16816(acc[1][nt], cH, bH[nb][p], bH[nb][p + 1]);
                        MMA16816(acc[1][nt], cH, bL[nb][p], bL[nb][p + 1]);
                        MMA16816(acc[1][nt], cL, bH[nb][p], bH[nb][p + 1]);
                    }
                }
            }
            // ---- V: single product ----
            if (cbw < nV) {
                LDSM4(bH[0], wb + WVHI + offB[ks]);
                if (cbw + 16 < nV) LDSM4(bH[1], wb + WVHI + offB[ks] + 1024);
                const uint32_t* vH = (const uint32_t*)&aVH[ks];
                #pragma unroll
                for (int nt = 0; nt < 4; nt++) {
                    if (cbw + nt * 8 < nV) {
                        const int nb = nt >> 1, p = (nt & 1) * 2;
                        MMA16816(acc[2][nt], vH, bH[nb][p], bH[nb][p + 1]);
                    }
                }
            }
        }
    };

    // ---- prologue: W groups for chunks 0,1 in flight ----
    cpaW(0);
    cpaW(1);

    for (int c = 0; c < NCHUNK; c++) {
        // Outstanding at top: W(c) [if not yet done], W(c+1). CPWAIT(1) -> W(c) arrived.
        if (c < NCHUNK - 1) { CPWAIT(1); } else { CPWAIT(0); }
        __syncthreads();           // all warps past compute(c-1); ring slot freed
        if (c + 2 < NCHUNK) cpaW(c + 2);
        compute(c);
    }
    __syncthreads();               // drain before smem reuse by epilogue

    // ---- epilogue: dump accs to smem (reuse W buffers), per-row softmax ----
    {
        float* sepi = (float*)dsm;
        const int g = lane >> 2, t = lane & 3;
        #pragma unroll
        for (int m = 0; m < 3; m++)
            #pragma unroll
            for (int nt = 0; nt < 4; nt++) {
                float* p = sepi + (size_t)((m * 64 + wm * 16 + g) * ESTR
                                           + wn * 32 + nt * 8 + 2 * t);
                p[0] = acc[m][nt][0];
                p[1] = acc[m][nt][1];
                p[8 * ESTR]     = acc[m][nt][2];
                p[8 * ESTR + 1] = acc[m][nt][3];
            }
        __syncthreads();

        const int row = tid >> 2, qd = tid & 3;    // thread = (row, 16-col quarter)
        float q[16], k[16], v[16];
        #pragma unroll
        for (int j = 0; j < 4; j++) {
            *(float4*)&q[j * 4] = *(float4*)&sepi[(0 * 64 + row) * ESTR + qd * 16 + j * 4];
            *(float4*)&k[j * 4] = *(float4*)&sepi[(1 * 64 + row) * ESTR + qd * 16 + j * 4];
            *(float4*)&v[j * 4] = *(float4*)&sepi[(2 * 64 + row) * ESTR + qd * 16 + j * 4];
        }
        float l[16];
        #pragma unroll
        for (int j = 0; j < 16; j++) {
            l[j] = q[j] * k[j] * 0.125f;
            if (qd * 16 + j >= vlen) l[j] -= 1e12f;
        }
        float mx = l[0];
        #pragma unroll
        for (int j = 1; j < 16; j++) mx = fmaxf(mx, l[j]);
        mx = fmaxf(mx, __shfl_xor_sync(0xffffffffu, mx, 1));
        mx = fmaxf(mx, __shfl_xor_sync(0xffffffffu, mx, 2));
        float sum = 0.f;
        #pragma unroll
        for (int j = 0; j < 16; j++) { l[j] = expf(l[j] - mx); sum += l[j]; }
        sum += __shfl_xor_sync(0xffffffffu, sum, 1);
        sum += __shfl_xor_sync(0xffffffffu, sum, 2);
        float sc = 1.0f / sum;
        if (s0 + row >= qlen) sc = 0.f;        // qmask
        float* op = outbase + (size_t)row * 512 + qd * 16;
        #pragma unroll
        for (int j = 0; j < 4; j++) {
            float4 o4 = make_float4(l[j * 4 + 0] * v[j * 4 + 0] * sc,
                                    l[j * 4 + 1] * v[j * 4 + 1] * sc,
                                    l[j * 4 + 2] * v[j * 4 + 2] * sc,
                                    l[j * 4 + 3] * v[j * 4 + 3] * sc);
            *(float4*)(op + j * 4) = o4;
        }
    }
}

// ---------------- launch ----------------
extern "C" void kernel_launch(void* const* d_in, const int* in_sizes, int n_in,
                              void* d_out, int out_size) {
    (void)in_sizes; (void)n_in; (void)out_size;
    const float* Qs = (const float*)d_in[0];
    const float* Ks = (const float*)d_in[1];
    const float* Vs = (const float*)d_in[2];
    const int*   Ql = (const int*)d_in[3];
    const int*   Vl = (const int*)d_in[4];
    const float* WQ = (const float*)d_in[5];
    const float* WK = (const float*)d_in[6];
    const float* WV = (const float*)d_in[7];

    static int smem_set = 0;
    if (!smem_set) {
        cudaFuncSetAttribute(gemm_attn, cudaFuncAttributeMaxDynamicSharedMemorySize,
                             SMEM_T);
        smem_set = 1;
    }

    prep_all<<<XFB + 3072, 256>>>(Qs, Ks, Vs, Ql, WQ, WK, WV);
    gemm_attn<<<dim3(8, 512), 256, SMEM_T>>>(Ql, Vl, (float*)d_out);
}

// round 17
// speedup vs baseline: 1.1517x; 1.1517x over previous
#include <cuda_runtime.h>
#include <cuda_fp16.h>
#include <cstdint>

// ---------------- scratch (static __device__, no allocs) ----------------
#define XN (3u*32768u*512u)
#define WN (3u*512u*512u)
__device__ __half g_xhi[XN];
__device__ __half g_xlo[XN];
__device__ __half g_wthi[WN];   // [m][n][k] fp16, K-major (W transposed)
__device__ __half g_wtlo[WN];

__device__ __forceinline__ uint32_t smem_u32(const void* p) {
    uint32_t a;
    asm("{ .reg .u64 t; cvta.to.shared.u64 t, %1; cvt.u32.u64 %0, t; }" : "=r"(a) : "l"(p));
    return a;
}

#define LDSM4(r, a) \
    asm volatile("ldmatrix.sync.aligned.m8n8.x4.shared.b16 {%0,%1,%2,%3}, [%4];" \
        : "=r"((r)[0]), "=r"((r)[1]), "=r"((r)[2]), "=r"((r)[3]) : "r"(a))

#define MMA16816(c, a, b0, b1) \
    asm volatile("mma.sync.aligned.m16n8k16.row.col.f32.f16.f16.f32 " \
        "{%0,%1,%2,%3},{%4,%5,%6,%7},{%8,%9},{%0,%1,%2,%3};" \
        : "+f"((c)[0]), "+f"((c)[1]), "+f"((c)[2]), "+f"((c)[3]) \
        : "r"((a)[0]), "r"((a)[1]), "r"((a)[2]), "r"((a)[3]), "r"(b0), "r"(b1))

#define CPA16(dst, src) \
    asm volatile("cp.async.cg.shared.global [%0], [%1], 16;" :: "r"(dst), "l"(src))
#define CPCOMMIT() asm volatile("cp.async.commit_group;" ::: "memory")
#define CPWAIT(n)  asm volatile("cp.async.wait_group %0;" :: "n"(n) : "memory")

// split 8 fp32 -> 8 fp16 hi + 8 fp16 lo (bit-identical across all rounds)
__device__ __forceinline__ void cvt8(const float4& a, const float4& b, uint4& hi, uint4& lo) {
    float f[8] = {a.x, a.y, a.z, a.w, b.x, b.y, b.z, b.w};
    union { __half h[8]; uint4 u; } H, L;
    #pragma unroll
    for (int i = 0; i < 8; i++) {
        H.h[i] = __float2half_rn(f[i]);
        L.h[i] = __float2half_rn(f[i] - __half2float(H.h[i]));
    }
    hi = H.u; lo = L.u;
}
__device__ __forceinline__ void cvt8hi(const float4& a, const float4& b, uint4& hi) {
    float f[8] = {a.x, a.y, a.z, a.w, b.x, b.y, b.z, b.w};
    union { __half h[8]; uint4 u; } H;
    #pragma unroll
    for (int i = 0; i < 8; i++) H.h[i] = __float2half_rn(f[i]);
    hi = H.u;
}

// ---------------- fused prep kernel (1024-thread blocks) ----------------
// blocks [0, 6144): X split, 16 rows per block (64 threads/row, 8 floats/thread)
// blocks [6144, 6912): W transpose+split, 1024 elems per block
#define XB16 6144
__global__ void __launch_bounds__(1024)
prep_all(const float* __restrict__ Qs, const float* __restrict__ Ks,
         const float* __restrict__ Vs, const int* __restrict__ Qlen,
         const float* __restrict__ WQ, const float* __restrict__ WK,
         const float* __restrict__ WV) {
    if (blockIdx.x < XB16) {
        int rid = blockIdx.x * 16 + (threadIdx.x >> 6);   // row id in 3*32768
        int t = threadIdx.x & 63;                         // 8 floats each
        int m = rid >> 15;
        int gr = rid & 32767;
        int b = gr >> 12, s = gr & 4095;
        if (s < ((Qlen[b] + 63) & ~63)) {
            const float* X = (m == 0) ? Qs : (m == 1) ? Ks : Vs;
            const float4* src = (const float4*)(X + ((size_t)gr << 9)) + t * 2;
            float4 va = src[0], vb = src[1];
            size_t o = (((size_t)m << 15) + gr) * 512 + t * 8;
            uint4 hi, lo;
            if (m < 2) {
                cvt8(va, vb, hi, lo);
                *(uint4*)(g_xhi + o) = hi;
                *(uint4*)(g_xlo + o) = lo;
            } else {
                cvt8hi(va, vb, hi);
                *(uint4*)(g_xhi + o) = hi;
            }
        }
    } else {
        int idx = (blockIdx.x - XB16) * 1024 + threadIdx.x;   // 3*512*512, [m][n][k]
        int m = idx >> 18;
        int r = idx & 262143;
        int n = r >> 9, k = r & 511;
        const float* W = (m == 0) ? WQ : (m == 1) ? WK : WV;
        float x = W[(size_t)k * 512 + n];
        __half h = __float2half_rn(x);
        g_wthi[idx] = h;
        if (m < 2) g_wtlo[idx] = __float2half_rn(x - __half2float(h));
    }
}

// ---------------- fused GEMM (HMMA) + softmax epilogue ----------------
// CTA: 64 rows x 1 head (N=64), 256 threads, 8 warps (warp tile 16x32), 2 CTAs/SM.
// WARP REMAP (round-17 fix): wm = wid&3, wn = wid>>2. SMSP = wid&3, so each SMSP
// owns one wn=0 and one wn=1 warp -> V_len culling of wn=1 shortens the critical
// path instead of idling SMSPs 1,3 (the R15 wn=wid&1 imbalance).
// All operands via cp.async: X 2-stage ring (depth 1), W 3-stage ring (depth 2).
// ONE __syncthreads per chunk; G_c = {X(c+1), W(c+2)} issued post-barrier.
// Q/K 3-product fp16 split; V single product; V_len culling (bit-exact output).
// Tile layout: 64 rows x 64B, phys 16B-col = c ^ ((r>>1)&3)  (round-10 proven).
#define XQHI 0
#define XQLO 4096
#define XKHI 8192
#define XKLO 12288
#define XVHI 16384
#define XS_B 20480
#define WQHI 0
#define WQLO 4096
#define WKHI 8192
#define WKLO 12288
#define WVHI 16384
#define WS_B 20480
#define WBASE 40960
#define SMEM_T 102400
#define NCHUNK  16
#define ESTR    68               // floats per row in epilogue smem

__global__ void __launch_bounds__(256, 2)
gemm_attn(const int* __restrict__ Qlen, const int* __restrict__ Vlen, float* __restrict__ out) {
    extern __shared__ __align__(16) char dsm[];

    const int h = blockIdx.x;                  // head 0..7 (fastest -> X L2 reuse)
    const int tile = blockIdx.y;               // 0..511
    const int b = tile >> 6;
    const int s0 = (tile & 63) << 6;
    const int tid = threadIdx.x;
    const int qlen = Qlen[b];
    float* outbase = out + ((size_t)(b * 4096 + s0)) * 512 + h * 64;

    if (s0 >= qlen) {                          // whole tile masked: write zeros
        #pragma unroll
        for (int i = 0; i < 4; i++) {
            int lin = tid + i * 256;
            int r = lin >> 4, c4 = lin & 15;
            *(float4*)(outbase + (size_t)r * 512 + c4 * 4) = make_float4(0.f, 0.f, 0.f, 0.f);
        }
        return;
    }

    const int vlen = Vlen[b];
    const int nQK = vlen;                      // head-cols of Q/K needed
    const int nV  = (vlen == 0) ? 64 : vlen;   // head-cols of V needed
    const int nWQK = (nQK + 15) & ~15;         // W rows to load (LDSM coverage)
    const int nWV  = (nV + 15) & ~15;

    const uint32_t sbase = smem_u32(dsm);
    const int lane = tid & 31, wid = tid >> 5;
    const int wm = wid & 3, wn = wid >> 2;     // REMAPPED: SMSP-balanced culling
    const int cbw = wn * 32;                   // col base of this warp

    // ldmatrix logical mapping, swizzled physical address (16B-col c ^= (r>>1)&3)
    const int rA = wm * 16 + ((lane >> 3) & 1) * 8 + (lane & 7);
    const int cA = (lane >> 4) & 1;
    const int swA = (rA >> 1) & 3;
    const int rB = wn * 32 + ((lane >> 4) & 1) * 8 + (lane & 7);
    const int cB = (lane >> 3) & 1;
    const int swB = (rB >> 1) & 3;
    uint32_t offA[2], offB[2];
    #pragma unroll
    for (int ks = 0; ks < 2; ks++) {
        offA[ks] = (uint32_t)(rA * 64 + (((ks * 2 + cA) ^ swA) << 4));
        offB[ks] = (uint32_t)(rB * 64 + (((ks * 2 + cB) ^ swB) << 4));
    }

    float acc[3][4][4];
    #pragma unroll
    for (int m = 0; m < 3; m++)
        #pragma unroll
        for (int nt = 0; nt < 4; nt++)
            #pragma unroll
            for (int q = 0; q < 4; q++) acc[m][nt][q] = 0.f;

    const size_t xrow = (size_t)(b * 4096 + s0);

    // loader: thread -> row tid>>2 (0..63), 16B-col tid&3; 1 CPA16 per tile
    const int lr = tid >> 2, cc = tid & 3;
    const uint32_t po = (uint32_t)(lr << 6) + ((((uint32_t)cc) ^ ((lr >> 1) & 3)) << 4);

    auto cpaX = [&](int c) {
        const int kk0 = c << 5;
        const uint32_t xb = sbase + (c & 1) * XS_B;
        const size_t o0 = ((size_t)(0 << 15) + xrow + lr) * 512 + kk0 + cc * 8;
        const size_t o1 = ((size_t)(1 << 15) + xrow + lr) * 512 + kk0 + cc * 8;
        const size_t o2 = ((size_t)(2 << 15) + xrow + lr) * 512 + kk0 + cc * 8;
        if (nQK > 0) {
            CPA16(xb + XQHI + po, g_xhi + o0);
            CPA16(xb + XQLO + po, g_xlo + o0);
            CPA16(xb + XKHI + po, g_xhi + o1);
            CPA16(xb + XKLO + po, g_xlo + o1);
        }
        CPA16(xb + XVHI + po, g_xhi + o2);
    };
    auto cpaW = [&](int c) {
        const int kk0 = c << 5;
        const uint32_t wb = sbase + WBASE + (c % 3) * WS_B;
        const size_t w0 = ((size_t)(0 * 512 + h * 64 + lr)) * 512 + kk0 + cc * 8;
        const size_t w1 = ((size_t)(1 * 512 + h * 64 + lr)) * 512 + kk0 + cc * 8;
        const size_t w2 = ((size_t)(2 * 512 + h * 64 + lr)) * 512 + kk0 + cc * 8;
        if (lr < nWQK) {
            CPA16(wb + WQHI + po, g_wthi + w0);
            CPA16(wb + WQLO + po, g_wtlo + w0);
            CPA16(wb + WKHI + po, g_wthi + w1);
            CPA16(wb + WKLO + po, g_wtlo + w1);
        }
        if (lr < nWV) CPA16(wb + WVHI + po, g_wthi + w2);
    };

    auto compute = [&](int c) {
        const uint32_t xb = sbase + (c & 1) * XS_B;
        const uint32_t wb = sbase + WBASE + (c % 3) * WS_B;
        #pragma unroll
        for (int ks = 0; ks < 2; ks++) {
            uint32_t aH[4], aL[4], bH[2][4], bL[2][4];
            if (cbw < nQK) {
                // ---- Q: 3 products ----
                LDSM4(aH, xb + XQHI + offA[ks]);
                LDSM4(aL, xb + XQLO + offA[ks]);
                LDSM4(bH[0], wb + WQHI + offB[ks]);
                LDSM4(bL[0], wb + WQLO + offB[ks]);
                if (cbw + 16 < nQK) {
                    LDSM4(bH[1], wb + WQHI + offB[ks] + 1024);
                    LDSM4(bL[1], wb + WQLO + offB[ks] + 1024);
                }
                #pragma unroll
                for (int nt = 0; nt < 4; nt++) {
                    if (cbw + nt * 8 < nQK) {
                        const int nb = nt >> 1, p = (nt & 1) * 2;
                        MMA16816(acc[0][nt], aH, bH[nb][p], bH[nb][p + 1]);
                        MMA16816(acc[0][nt], aH, bL[nb][p], bL[nb][p + 1]);
                        MMA16816(acc[0][nt], aL, bH[nb][p], bH[nb][p + 1]);
                    }
                }
                // ---- K: 3 products ----
                LDSM4(aH, xb + XKHI + offA[ks]);
                LDSM4(aL, xb + XKLO + offA[ks]);
                LDSM4(bH[0], wb + WKHI + offB[ks]);
                LDSM4(bL[0], wb + WKLO + offB[ks]);
                if (cbw + 16 < nQK) {
                    LDSM4(bH[1], wb + WKHI + offB[ks] + 1024);
                    LDSM4(bL[1], wb + WKLO + offB[ks] + 1024);
                }
                #pragma unroll
                for (int nt = 0; nt < 4; nt++) {
                    if (cbw + nt * 8 < nQK) {
                        const int nb = nt >> 1, p = (nt & 1) * 2;
                        MMA16816(acc[1][nt], aH, bH[nb][p], bH[nb][p + 1]);
                        MMA16816(acc[1][nt], aH, bL[nb][p], bL[nb][p + 1]);
                        MMA16816(acc[1][nt], aL, bH[nb][p], bH[nb][p + 1]);
                    }
                }
            }
            // ---- V: single product ----
            if (cbw < nV) {
                LDSM4(aH, xb + XVHI + offA[ks]);
                LDSM4(bH[0], wb + WVHI + offB[ks]);
                if (cbw + 16 < nV) LDSM4(bH[1], wb + WVHI + offB[ks] + 1024);
                #pragma unroll
                for (int nt = 0; nt < 4; nt++) {
                    if (cbw + nt * 8 < nV) {
                        const int nb = nt >> 1, p = (nt & 1) * 2;
                        MMA16816(acc[2][nt], aH, bH[nb][p], bH[nb][p + 1]);
                    }
                }
            }
        }
    };

    // ---- prologue: X(0)+W(0) in one group, W(1) in another ----
    cpaX(0); cpaW(0); CPCOMMIT();
    cpaW(1); CPCOMMIT();

    for (int c = 0; c < NCHUNK; c++) {
        CPWAIT(0);                 // G_{c-1} (carrying X(c), W(c+1)) fully arrived
        __syncthreads();           // all warps past compute(c-1); stages freed
        if (c + 1 < NCHUNK) cpaX(c + 1);   // slot (c+1)&1 — freed at this barrier
        if (c + 2 < NCHUNK) cpaW(c + 2);   // slot (c+2)%3 == (c-1)%3 — freed too
        CPCOMMIT();                // one group per chunk; in flight during compute
        compute(c);
    }
    __syncthreads();               // drain before smem reuse by epilogue

    // ---- epilogue: dump accs to smem (reuse tile buffers), per-row softmax ----
    {
        float* sepi = (float*)dsm;
        const int g = lane >> 2, t = lane & 3;
        #pragma unroll
        for (int m = 0; m < 3; m++)
            #pragma unroll
            for (int nt = 0; nt < 4; nt++) {
                float* p = sepi + (size_t)((m * 64 + wm * 16 + g) * ESTR
                                           + wn * 32 + nt * 8 + 2 * t);
                p[0] = acc[m][nt][0];
                p[1] = acc[m][nt][1];
                p[8 * ESTR]     = acc[m][nt][2];
                p[8 * ESTR + 1] = acc[m][nt][3];
            }
        __syncthreads();

        const int row = tid >> 2, qd = tid & 3;    // thread = (row, 16-col quarter)
        float q[16], k[16], v[16];
        #pragma unroll
        for (int j = 0; j < 4; j++) {
            *(float4*)&q[j * 4] = *(float4*)&sepi[(0 * 64 + row) * ESTR + qd * 16 + j * 4];
            *(float4*)&k[j * 4] = *(float4*)&sepi[(1 * 64 + row) * ESTR + qd * 16 + j * 4];
            *(float4*)&v[j * 4] = *(float4*)&sepi[(2 * 64 + row) * ESTR + qd * 16 + j * 4];
        }
        float l[16];
        #pragma unroll
        for (int j = 0; j < 16; j++) {
            l[j] = q[j] * k[j] * 0.125f;
            if (qd * 16 + j >= vlen) l[j] -= 1e12f;
        }
        float mx = l[0];
        #pragma unroll
        for (int j = 1; j < 16; j++) mx = fmaxf(mx, l[j]);
        mx = fmaxf(mx, __shfl_xor_sync(0xffffffffu, mx, 1));
        mx = fmaxf(mx, __shfl_xor_sync(0xffffffffu, mx, 2));
        float sum = 0.f;
        #pragma unroll
        for (int j = 0; j < 16; j++) { l[j] = expf(l[j] - mx); sum += l[j]; }
        sum += __shfl_xor_sync(0xffffffffu, sum, 1);
        sum += __shfl_xor_sync(0xffffffffu, sum, 2);
        float sc = 1.0f / sum;
        if (s0 + row >= qlen) sc = 0.f;        // qmask
        float* op = outbase + (size_t)row * 512 + qd * 16;
        #pragma unroll
        for (int j = 0; j < 4; j++) {
            float4 o4 = make_float4(l[j * 4 + 0] * v[j * 4 + 0] * sc,
                                    l[j * 4 + 1] * v[j * 4 + 1] * sc,
                                    l[j * 4 + 2] * v[j * 4 + 2] * sc,
                                    l[j * 4 + 3] * v[j * 4 + 3] * sc);
            *(float4*)(op + j * 4) = o4;
        }
    }
}

// ---------------- launch ----------------
extern "C" void kernel_launch(void* const* d_in, const int* in_sizes, int n_in,
                              void* d_out, int out_size) {
    (void)in_sizes; (void)n_in; (void)out_size;
    const float* Qs = (const float*)d_in[0];
    const float* Ks = (const float*)d_in[1];
    const float* Vs = (const float*)d_in[2];
    const int*   Ql = (const int*)d_in[3];
    const int*   Vl = (const int*)d_in[4];
    const float* WQ = (const float*)d_in[5];
    const float* WK = (const float*)d_in[6];
    const float* WV = (const float*)d_in[7];

    static int smem_set = 0;
    if (!smem_set) {
        cudaFuncSetAttribute(gemm_attn, cudaFuncAttributeMaxDynamicSharedMemorySize,
                             SMEM_T);
        smem_set = 1;
    }

    prep_all<<<XB16 + 768, 1024>>>(Qs, Ks, Vs, Ql, WQ, WK, WV);
    gemm_attn<<<dim3(8, 512), 256, SMEM_T>>>(Ql, Vl, (float*)d_out);
}